// round 16
// baseline (speedup 1.0000x reference)
#include <cuda_runtime.h>
#include <cuda_fp16.h>
#include <cstdint>

// Problem constants
#define SS   96
#define BB   16
#define DD   512
#define HIDN 128
#define NR   (SS * BB)   // 1536 rows
#define NCH  8           // k chunks of 64

// Intermediate activations
__device__ float g_ha[NR * HIDN];
__device__ float g_hb[NR * HIDN];
// Stage2 h-split partials: [hhalf][ (i*SS+j)*BB+b)*2 + c ]
__device__ float g_part[2][SS * SS * BB * 2];

// Pre-converted, pre-swizzled fp16 operands (chunk-major 128B rows in SW128
// smem image).
__device__ __align__(256) __half g_X16[2][NCH * NR * 64];
__device__ __align__(256) __half g_W16[2][NCH * HIDN * 64];

// ---------------------------------------------------------------------------
// Helpers
// ---------------------------------------------------------------------------
__device__ __forceinline__ unsigned smem_u32(const void* p)
{
    unsigned a;
    asm("{ .reg .u64 t; cvta.to.shared.u64 t, %1; cvt.u32.u64 %0, t; }"
        : "=r"(a) : "l"(p));
    return a;
}

__device__ __forceinline__ unsigned sw128(unsigned byte_off)
{
    return byte_off ^ ((byte_off >> 3) & 0x70);
}

__device__ __forceinline__ uint2 cvt_h4(float4 v)
{
    __half2 h01 = __float22half2_rn(make_float2(v.x, v.y));
    __half2 h23 = __float22half2_rn(make_float2(v.z, v.w));
    uint2 r;
    r.x = *reinterpret_cast<unsigned*>(&h01);
    r.y = *reinterpret_cast<unsigned*>(&h23);
    return r;
}

__device__ __forceinline__ void ldsm_x4(
    uint32_t& r0, uint32_t& r1, uint32_t& r2, uint32_t& r3, unsigned addr)
{
    asm volatile("ldmatrix.sync.aligned.m8n8.x4.shared.b16 {%0,%1,%2,%3}, [%4];"
                 : "=r"(r0), "=r"(r1), "=r"(r2), "=r"(r3) : "r"(addr));
}

__device__ __forceinline__ void mma_f16(
    float* d, uint32_t a0, uint32_t a1, uint32_t a2, uint32_t a3,
    uint32_t b0, uint32_t b1)
{
    asm volatile(
        "mma.sync.aligned.m16n8k16.row.col.f32.f16.f16.f32 "
        "{%0,%1,%2,%3}, {%4,%5,%6,%7}, {%8,%9}, {%0,%1,%2,%3};"
        : "+f"(d[0]), "+f"(d[1]), "+f"(d[2]), "+f"(d[3])
        : "r"(a0), "r"(a1), "r"(a2), "r"(a3), "r"(b0), "r"(b1));
}

__device__ __forceinline__ void cp16(unsigned dst, const void* src)
{
    asm volatile("cp.async.cg.shared.global [%0], [%1], 16;" :: "r"(dst), "l"(src));
}
__device__ __forceinline__ void cp_commit() { asm volatile("cp.async.commit_group;"); }
__device__ __forceinline__ void cp_wait1()  { asm volatile("cp.async.wait_group 1;"); }
__device__ __forceinline__ void cp_wait0()  { asm volatile("cp.async.wait_group 0;"); }

// Packed f32x2 ops (stage2)
__device__ __forceinline__ unsigned long long add2(
    unsigned long long a, unsigned long long b)
{
    unsigned long long d;
    asm("add.rn.f32x2 %0, %1, %2;" : "=l"(d) : "l"(a), "l"(b));
    return d;
}
__device__ __forceinline__ unsigned long long ffma2(
    unsigned long long a, unsigned long long b, unsigned long long c)
{
    unsigned long long d;
    asm("fma.rn.f32x2 %0, %1, %2, %3;" : "=l"(d) : "l"(a), "l"(b), "l"(c));
    return d;
}
__device__ __forceinline__ unsigned long long relu2(unsigned long long x)
{
    unsigned long long r;
    asm("{\n\t.reg .f32 lo, hi;\n\t"
        "mov.b64 {lo, hi}, %1;\n\t"
        "max.f32 lo, lo, 0f00000000;\n\t"
        "max.f32 hi, hi, 0f00000000;\n\t"
        "mov.b64 %0, {lo, hi};\n\t}"
        : "=l"(r) : "l"(x));
    return r;
}
__device__ __forceinline__ float2 unpk2(unsigned long long v)
{
    float2 f;
    asm("mov.b64 {%0, %1}, %2;" : "=f"(f.x), "=f"(f.y) : "l"(v));
    return f;
}

// ---------------------------------------------------------------------------
// Prep kernel: convert X0/X1/W1 to fp16, pre-swizzled chunk-row layout.
// Each thread handles 4 consecutive float4 (64B along k) -> 2x 16B stores
// (i pairs {0,1},{2,3} share the swizzle XOR since bit3 isn't in the mask).
// Threads: X: 2*1536*32 = 98304; W: 2*128*32 = 8192. Total 106496 -> 416 blks.
// ---------------------------------------------------------------------------
#define PREP_X_THREADS (2 * NR * 32)
#define PREP_W_THREADS (2 * HIDN * 32)

__global__ __launch_bounds__(256) void prep_kernel(
    const float* __restrict__ X0, const float* __restrict__ X1,
    const float* __restrict__ W1)
{
    const int idx = blockIdx.x * 256 + threadIdx.x;
    if (idx < PREP_X_THREADS) {
        const int z  = idx >= (NR * 32);
        const int i  = idx - z * (NR * 32);
        const int r  = i >> 5;        // 0..1535
        const int qs = i & 31;        // 64B segment along k
        const float* __restrict__ X = z ? X1 : X0;
        const float* src = &X[(size_t)r * DD + qs * 16];
        float4 v0 = reinterpret_cast<const float4*>(src)[0];
        float4 v1 = reinterpret_cast<const float4*>(src)[1];
        float4 v2 = reinterpret_cast<const float4*>(src)[2];
        float4 v3 = reinterpret_cast<const float4*>(src)[3];
        const int c   = qs >> 2;              // chunk
        const int ql0 = (qs & 3) * 4;         // first f4-group in chunk row
        const unsigned mask = (unsigned)(r & 7) << 4;
        char* base = reinterpret_cast<char*>(g_X16[z]) + (size_t)(c * NR + r) * 128;
        uint2 a = cvt_h4(v0), b = cvt_h4(v1);
        uint4 s0 = make_uint4(a.x, a.y, b.x, b.y);
        uint2 cc = cvt_h4(v2), dd = cvt_h4(v3);
        uint4 s1 = make_uint4(cc.x, cc.y, dd.x, dd.y);
        *reinterpret_cast<uint4*>(base + ((unsigned)(ql0 * 8) ^ mask)) = s0;
        *reinterpret_cast<uint4*>(base + ((unsigned)((ql0 + 2) * 8) ^ mask)) = s1;
    } else if (idx < PREP_X_THREADS + PREP_W_THREADS) {
        const int j  = idx - PREP_X_THREADS;
        const int z  = j >= (HIDN * 32);
        const int i  = j - z * (HIDN * 32);
        const int h  = i >> 5;        // 0..127
        const int qs = i & 31;
        const float* src = &W1[(size_t)h * (2 * DD) + z * DD + qs * 16];
        float4 v0 = reinterpret_cast<const float4*>(src)[0];
        float4 v1 = reinterpret_cast<const float4*>(src)[1];
        float4 v2 = reinterpret_cast<const float4*>(src)[2];
        float4 v3 = reinterpret_cast<const float4*>(src)[3];
        const int c   = qs >> 2;
        const int ql0 = (qs & 3) * 4;
        const unsigned mask = (unsigned)(h & 7) << 4;
        char* base = reinterpret_cast<char*>(g_W16[z]) + (size_t)(c * HIDN + h) * 128;
        uint2 a = cvt_h4(v0), b = cvt_h4(v1);
        uint4 s0 = make_uint4(a.x, a.y, b.x, b.y);
        uint2 cc = cvt_h4(v2), dd = cvt_h4(v3);
        uint4 s1 = make_uint4(cc.x, cc.y, dd.x, dd.y);
        *reinterpret_cast<uint4*>(base + ((unsigned)(ql0 * 8) ^ mask)) = s0;
        *reinterpret_cast<uint4*>(base + ((unsigned)((ql0 + 2) * 8) ^ mask)) = s1;
    }
}

// ---------------------------------------------------------------------------
// Stage 1: fp16 GEMM, pure cp.async fills (unchanged from R15).
// M=32, N=64; 8 warps; 3-buffer pipeline. Grid (48,2,2)=192.
// ---------------------------------------------------------------------------
#define SA_BYTES 4096
#define SB_BYTES 8192
#define SA_OFF(i) ((i) * SA_BYTES)
#define SB_OFF(i) (3 * SA_BYTES + (i) * SB_BYTES)
#define S1_SMEM  (3 * SA_BYTES + 3 * SB_BYTES)   // 36864

__global__ __launch_bounds__(256) void stage1_kernel(const float* __restrict__ b1)
{
    extern __shared__ char smem[];
    const unsigned sbase = smem_u32(smem);

    const int mt = blockIdx.x;
    const int nt = blockIdx.y;
    const int z  = blockIdx.z;
    const int m0 = mt * 32;
    const int n0 = nt * 64;

    const char* __restrict__ Xg = reinterpret_cast<const char*>(g_X16[z]);
    const char* __restrict__ Wg = reinterpret_cast<const char*>(g_W16[z]);
    float* __restrict__ C = z ? g_hb : g_ha;

    const int tid  = threadIdx.x;
    const int wid  = tid >> 5;
    const int lane = tid & 31;
    const int wm   = wid & 1;
    const int wn   = wid >> 1;

    const int a_row = tid >> 3;
    const int a_seg = tid & 7;
    const unsigned aDst = a_row * 128u + a_seg * 16u;
    const int b_row0 = tid >> 3;
    const int b_row1 = (tid + 256) >> 3;
    const int b_seg  = tid & 7;
    const unsigned bDst0 = b_row0 * 128u + b_seg * 16u;
    const unsigned bDst1 = b_row1 * 128u + b_seg * 16u;

    auto fill = [&](int c, int buf) {
        cp16(sbase + SA_OFF(buf) + aDst,
             Xg + (size_t)(c * NR + m0 + a_row) * 128 + a_seg * 16);
        cp16(sbase + SB_OFF(buf) + bDst0,
             Wg + (size_t)(c * HIDN + n0 + b_row0) * 128 + b_seg * 16);
        cp16(sbase + SB_OFF(buf) + bDst1,
             Wg + (size_t)(c * HIDN + n0 + b_row1) * 128 + b_seg * 16);
        cp_commit();
    };

    fill(0, 0);
    fill(1, 1);

    const int a_r  = (lane & 15);
    const int a_ch = (lane >> 4);
    const int b_n  = (lane & 7) + ((lane >> 4) << 3);
    const int b_ch = (lane >> 3) & 1;

    float acc[2][4];
    #pragma unroll
    for (int ni = 0; ni < 2; ni++)
        #pragma unroll
        for (int r = 0; r < 4; r++) acc[ni][r] = 0.0f;

    #pragma unroll 1
    for (int t = 0; t < NCH; t++) {
        if (t < NCH - 1) cp_wait1(); else cp_wait0();
        __syncthreads();
        if (t + 2 < NCH) fill(t + 2, (t + 2) % 3);

        const unsigned aH = sbase + SA_OFF(t % 3);
        const unsigned bH = sbase + SB_OFF(t % 3);

        #pragma unroll
        for (int ks = 0; ks < 4; ks++) {
            const unsigned kb = (unsigned)(ks * 32);
            uint32_t ah[4];
            {
                const unsigned off = sw128(
                    (unsigned)((wm * 16 + a_r) * 128) + kb + a_ch * 16);
                ldsm_x4(ah[0], ah[1], ah[2], ah[3], aH + off);
            }
            uint32_t bh[4];
            {
                const unsigned off = sw128(
                    (unsigned)((wn * 16 + b_n) * 128) + kb + b_ch * 16);
                ldsm_x4(bh[0], bh[1], bh[2], bh[3], bH + off);
            }
            #pragma unroll
            for (int ni = 0; ni < 2; ni++)
                mma_f16(acc[ni], ah[0], ah[1], ah[2], ah[3],
                        bh[2 * ni], bh[2 * ni + 1]);
        }
    }

    #pragma unroll
    for (int ni = 0; ni < 2; ni++) {
        const int row = m0 + wm * 16 + (lane >> 2);
        const int col = n0 + wn * 16 + ni * 8 + (lane & 3) * 2;
        float2 bias = make_float2(0.f, 0.f);
        if (z == 0)
            bias = *reinterpret_cast<const float2*>(&b1[col]);
        float2 o0, o1;
        o0.x = acc[ni][0] + bias.x;
        o0.y = acc[ni][1] + bias.y;
        o1.x = acc[ni][2] + bias.x;
        o1.y = acc[ni][3] + bias.y;
        *reinterpret_cast<float2*>(&C[(size_t)row * HIDN + col]) = o0;
        *reinterpret_cast<float2*>(&C[(size_t)(row + 8) * HIDN + col]) = o1;
    }
}

// ---------------------------------------------------------------------------
// Stage 2 partial: h-split halves of
//   out[i,j,b,c] = sum_h relu(ha'[i,b,h]+hb[j,b,h])*W2[c,h]
// Grid (3,3,32): blockIdx.z = b*2 + hhalf. 32x32 tile, 256 thr, 2x2/thread.
// Writes fp32 partials (no bias) to g_part[hhalf].
// ---------------------------------------------------------------------------
#define TI 32
#define TJ 32
#define HH 64     // h per half
#define PADH2 68  // 64+4 floats

__global__ __launch_bounds__(256) void stage2p_kernel(
    const float* __restrict__ W2)
{
    __shared__ float sA[TI][PADH2];
    __shared__ float sB[TJ][PADH2];
    __shared__ float sW2[2 * HH];

    const int i0    = blockIdx.x * TI;
    const int j0    = blockIdx.y * TJ;
    const int b     = blockIdx.z >> 1;
    const int hh    = blockIdx.z & 1;
    const int hbase = hh * HH;
    const int tid   = threadIdx.x;

    float* __restrict__ part = g_part[hh];

    #pragma unroll
    for (int p = 0; p < 2; p++) {
        const int q   = tid + p * 256;  // 0..511
        const int row = q >> 4;         // 0..31
        const int hq  = q & 15;         // float4 index in half
        float4 va = *reinterpret_cast<const float4*>(
            &g_ha[((size_t)(i0 + row) * BB + b) * HIDN + hbase + hq * 4]);
        *reinterpret_cast<float4*>(&sA[row][hq * 4]) = va;
        float4 vb = *reinterpret_cast<const float4*>(
            &g_hb[((size_t)(j0 + row) * BB + b) * HIDN + hbase + hq * 4]);
        *reinterpret_cast<float4*>(&sB[row][hq * 4]) = vb;
    }
    if (tid < 32) {
        const int ch = tid >> 4;    // channel
        const int q  = tid & 15;
        float4 w = *reinterpret_cast<const float4*>(
            &W2[ch * HIDN + hbase + q * 4]);
        *reinterpret_cast<float4*>(&sW2[ch * HH + q * 4]) = w;
    }
    __syncthreads();

    const int rg = tid >> 4;
    const int cg = tid & 15;

    unsigned long long acc[2][2][2];
    #pragma unroll
    for (int ii = 0; ii < 2; ii++)
        #pragma unroll
        for (int jj = 0; jj < 2; jj++) {
            acc[ii][jj][0] = 0ull;
            acc[ii][jj][1] = 0ull;
        }

    #pragma unroll
    for (int hq = 0; hq < HH / 4; hq++) {
        ulonglong2 a0 = *reinterpret_cast<const ulonglong2*>(&sA[rg][hq * 4]);
        ulonglong2 a1 = *reinterpret_cast<const ulonglong2*>(&sA[rg + 16][hq * 4]);
        ulonglong2 q0 = *reinterpret_cast<const ulonglong2*>(&sB[cg][hq * 4]);
        ulonglong2 q1 = *reinterpret_cast<const ulonglong2*>(&sB[cg + 16][hq * 4]);
        ulonglong2 w0 = *reinterpret_cast<const ulonglong2*>(&sW2[hq * 4]);
        ulonglong2 w1 = *reinterpret_cast<const ulonglong2*>(&sW2[HH + hq * 4]);

        const unsigned long long av[2][2] = {{a0.x, a0.y}, {a1.x, a1.y}};
        const unsigned long long qv[2][2] = {{q0.x, q0.y}, {q1.x, q1.y}};
        const unsigned long long wv[2][2] = {{w0.x, w0.y}, {w1.x, w1.y}};

        #pragma unroll
        for (int hp = 0; hp < 2; hp++) {
            #pragma unroll
            for (int ii = 0; ii < 2; ii++)
                #pragma unroll
                for (int jj = 0; jj < 2; jj++) {
                    unsigned long long v = relu2(add2(av[ii][hp], qv[jj][hp]));
                    acc[ii][jj][0] = ffma2(v, wv[0][hp], acc[ii][jj][0]);
                    acc[ii][jj][1] = ffma2(v, wv[1][hp], acc[ii][jj][1]);
                }
        }
    }

    #pragma unroll
    for (int ii = 0; ii < 2; ii++)
        #pragma unroll
        for (int jj = 0; jj < 2; jj++) {
            const int i = i0 + rg + ii * 16;
            const int j = j0 + cg + jj * 16;
            const size_t idx = (((size_t)i * SS + j) * BB + b) * 2;
            float2 p0 = unpk2(acc[ii][jj][0]);
            float2 p1 = unpk2(acc[ii][jj][1]);
            float2 o;
            o.x = p0.x + p0.y;
            o.y = p1.x + p1.y;
            *reinterpret_cast<float2*>(&part[idx]) = o;
        }
}

// ---------------------------------------------------------------------------
// Reduce: out = part0 + part1 + b2.  73728 float4 -> 288 blocks x 256 thr.
// ---------------------------------------------------------------------------
__global__ __launch_bounds__(256) void reduce_kernel(
    const float* __restrict__ b2, float* __restrict__ out)
{
    const int idx = blockIdx.x * 256 + threadIdx.x;   // float4 index
    const float bb0 = b2[0];
    const float bb1 = b2[1];
    float4 p0 = reinterpret_cast<const float4*>(g_part[0])[idx];
    float4 p1 = reinterpret_cast<const float4*>(g_part[1])[idx];
    float4 o;
    o.x = p0.x + p1.x + bb0;
    o.y = p0.y + p1.y + bb1;
    o.z = p0.z + p1.z + bb0;
    o.w = p0.w + p1.w + bb1;
    reinterpret_cast<float4*>(out)[idx] = o;
}

// ---------------------------------------------------------------------------
// Inputs: embeds, umask, qmask, embeds_cmp, W1, b1, W2, b2
// ---------------------------------------------------------------------------
extern "C" void kernel_launch(void* const* d_in, const int* in_sizes, int n_in,
                              void* d_out, int out_size)
{
    const float* embeds     = (const float*)d_in[0];
    const float* embeds_cmp = (const float*)d_in[3];
    const float* W1         = (const float*)d_in[4];
    const float* b1         = (const float*)d_in[5];
    const float* W2         = (const float*)d_in[6];
    const float* b2         = (const float*)d_in[7];
    float* out = (float*)d_out;

    cudaFuncSetAttribute(stage1_kernel,
                         cudaFuncAttributeMaxDynamicSharedMemorySize, S1_SMEM);

    const int prep_blocks = (PREP_X_THREADS + PREP_W_THREADS + 255) / 256;
    prep_kernel<<<prep_blocks, 256>>>(embeds, embeds_cmp, W1);
    stage1_kernel<<<dim3(48, 2, 2), 256, S1_SMEM>>>(b1);
    stage2p_kernel<<<dim3(3, 3, 32), 256>>>(W2);
    reduce_kernel<<<(SS * SS * BB * 2 / 4 + 255) / 256, 256>>>(b2, out);
}

// round 17
// speedup vs baseline: 1.1514x; 1.1514x over previous
#include <cuda_runtime.h>
#include <cuda_fp16.h>
#include <cstdint>

// Problem constants
#define SS   96
#define BB   16
#define DD   512
#define HIDN 128
#define NR   (SS * BB)   // 1536 rows
#define NCH  8           // k chunks of 64

// Intermediate activations
__device__ float g_ha[NR * HIDN];
__device__ float g_hb[NR * HIDN];

// Pre-converted, pre-swizzled fp16 operands (chunk-major 128B rows in SW128
// smem image).
__device__ __align__(256) __half g_X16[2][NCH * NR * 64];
__device__ __align__(256) __half g_W16[2][NCH * HIDN * 64];

// ---------------------------------------------------------------------------
// Helpers
// ---------------------------------------------------------------------------
__device__ __forceinline__ unsigned smem_u32(const void* p)
{
    unsigned a;
    asm("{ .reg .u64 t; cvta.to.shared.u64 t, %1; cvt.u32.u64 %0, t; }"
        : "=r"(a) : "l"(p));
    return a;
}

__device__ __forceinline__ unsigned sw128(unsigned byte_off)
{
    return byte_off ^ ((byte_off >> 3) & 0x70);
}

__device__ __forceinline__ uint2 cvt_h4(float4 v)
{
    __half2 h01 = __float22half2_rn(make_float2(v.x, v.y));
    __half2 h23 = __float22half2_rn(make_float2(v.z, v.w));
    uint2 r;
    r.x = *reinterpret_cast<unsigned*>(&h01);
    r.y = *reinterpret_cast<unsigned*>(&h23);
    return r;
}

__device__ __forceinline__ void ldsm_x4(
    uint32_t& r0, uint32_t& r1, uint32_t& r2, uint32_t& r3, unsigned addr)
{
    asm volatile("ldmatrix.sync.aligned.m8n8.x4.shared.b16 {%0,%1,%2,%3}, [%4];"
                 : "=r"(r0), "=r"(r1), "=r"(r2), "=r"(r3) : "r"(addr));
}

__device__ __forceinline__ void mma_f16(
    float* d, uint32_t a0, uint32_t a1, uint32_t a2, uint32_t a3,
    uint32_t b0, uint32_t b1)
{
    asm volatile(
        "mma.sync.aligned.m16n8k16.row.col.f32.f16.f16.f32 "
        "{%0,%1,%2,%3}, {%4,%5,%6,%7}, {%8,%9}, {%0,%1,%2,%3};"
        : "+f"(d[0]), "+f"(d[1]), "+f"(d[2]), "+f"(d[3])
        : "r"(a0), "r"(a1), "r"(a2), "r"(a3), "r"(b0), "r"(b1));
}

__device__ __forceinline__ void cp16(unsigned dst, const void* src)
{
    asm volatile("cp.async.cg.shared.global [%0], [%1], 16;" :: "r"(dst), "l"(src));
}
__device__ __forceinline__ void cp_commit() { asm volatile("cp.async.commit_group;"); }
__device__ __forceinline__ void cp_wait1()  { asm volatile("cp.async.wait_group 1;"); }
__device__ __forceinline__ void cp_wait0()  { asm volatile("cp.async.wait_group 0;"); }

// Packed f32x2 ops (stage2)
__device__ __forceinline__ unsigned long long add2(
    unsigned long long a, unsigned long long b)
{
    unsigned long long d;
    asm("add.rn.f32x2 %0, %1, %2;" : "=l"(d) : "l"(a), "l"(b));
    return d;
}
__device__ __forceinline__ unsigned long long ffma2(
    unsigned long long a, unsigned long long b, unsigned long long c)
{
    unsigned long long d;
    asm("fma.rn.f32x2 %0, %1, %2, %3;" : "=l"(d) : "l"(a), "l"(b), "l"(c));
    return d;
}
__device__ __forceinline__ unsigned long long relu2(unsigned long long x)
{
    unsigned long long r;
    asm("{\n\t.reg .f32 lo, hi;\n\t"
        "mov.b64 {lo, hi}, %1;\n\t"
        "max.f32 lo, lo, 0f00000000;\n\t"
        "max.f32 hi, hi, 0f00000000;\n\t"
        "mov.b64 %0, {lo, hi};\n\t}"
        : "=l"(r) : "l"(x));
    return r;
}
__device__ __forceinline__ float2 unpk2(unsigned long long v)
{
    float2 f;
    asm("mov.b64 {%0, %1}, %2;" : "=f"(f.x), "=f"(f.y) : "l"(v));
    return f;
}

// ---------------------------------------------------------------------------
// Prep kernel (R16 version): convert X0/X1/W1 to fp16, pre-swizzled
// chunk-row layout. 4 float4 per thread (MLP=4), 2x 16B swizzled stores.
// ---------------------------------------------------------------------------
#define PREP_X_THREADS (2 * NR * 32)
#define PREP_W_THREADS (2 * HIDN * 32)

__global__ __launch_bounds__(256) void prep_kernel(
    const float* __restrict__ X0, const float* __restrict__ X1,
    const float* __restrict__ W1)
{
    const int idx = blockIdx.x * 256 + threadIdx.x;
    if (idx < PREP_X_THREADS) {
        const int z  = idx >= (NR * 32);
        const int i  = idx - z * (NR * 32);
        const int r  = i >> 5;
        const int qs = i & 31;
        const float* __restrict__ X = z ? X1 : X0;
        const float* src = &X[(size_t)r * DD + qs * 16];
        float4 v0 = reinterpret_cast<const float4*>(src)[0];
        float4 v1 = reinterpret_cast<const float4*>(src)[1];
        float4 v2 = reinterpret_cast<const float4*>(src)[2];
        float4 v3 = reinterpret_cast<const float4*>(src)[3];
        const int c   = qs >> 2;
        const int ql0 = (qs & 3) * 4;
        const unsigned mask = (unsigned)(r & 7) << 4;
        char* base = reinterpret_cast<char*>(g_X16[z]) + (size_t)(c * NR + r) * 128;
        uint2 a = cvt_h4(v0), b = cvt_h4(v1);
        uint4 s0 = make_uint4(a.x, a.y, b.x, b.y);
        uint2 cc = cvt_h4(v2), dd = cvt_h4(v3);
        uint4 s1 = make_uint4(cc.x, cc.y, dd.x, dd.y);
        *reinterpret_cast<uint4*>(base + ((unsigned)(ql0 * 8) ^ mask)) = s0;
        *reinterpret_cast<uint4*>(base + ((unsigned)((ql0 + 2) * 8) ^ mask)) = s1;
    } else if (idx < PREP_X_THREADS + PREP_W_THREADS) {
        const int j  = idx - PREP_X_THREADS;
        const int z  = j >= (HIDN * 32);
        const int i  = j - z * (HIDN * 32);
        const int h  = i >> 5;
        const int qs = i & 31;
        const float* src = &W1[(size_t)h * (2 * DD) + z * DD + qs * 16];
        float4 v0 = reinterpret_cast<const float4*>(src)[0];
        float4 v1 = reinterpret_cast<const float4*>(src)[1];
        float4 v2 = reinterpret_cast<const float4*>(src)[2];
        float4 v3 = reinterpret_cast<const float4*>(src)[3];
        const int c   = qs >> 2;
        const int ql0 = (qs & 3) * 4;
        const unsigned mask = (unsigned)(h & 7) << 4;
        char* base = reinterpret_cast<char*>(g_W16[z]) + (size_t)(c * HIDN + h) * 128;
        uint2 a = cvt_h4(v0), b = cvt_h4(v1);
        uint4 s0 = make_uint4(a.x, a.y, b.x, b.y);
        uint2 cc = cvt_h4(v2), dd = cvt_h4(v3);
        uint4 s1 = make_uint4(cc.x, cc.y, dd.x, dd.y);
        *reinterpret_cast<uint4*>(base + ((unsigned)(ql0 * 8) ^ mask)) = s0;
        *reinterpret_cast<uint4*>(base + ((unsigned)((ql0 + 2) * 8) ^ mask)) = s1;
    }
}

// ---------------------------------------------------------------------------
// Stage 1: fp16 GEMM, pure cp.async fills (R15 version, measured ~3.3us).
// M=32, N=64; 8 warps; 3-buffer pipeline. Grid (48,2,2)=192.
// ---------------------------------------------------------------------------
#define SA_BYTES 4096
#define SB_BYTES 8192
#define SA_OFF(i) ((i) * SA_BYTES)
#define SB_OFF(i) (3 * SA_BYTES + (i) * SB_BYTES)
#define S1_SMEM  (3 * SA_BYTES + 3 * SB_BYTES)   // 36864

__global__ __launch_bounds__(256) void stage1_kernel(const float* __restrict__ b1)
{
    extern __shared__ char smem[];
    const unsigned sbase = smem_u32(smem);

    const int mt = blockIdx.x;
    const int nt = blockIdx.y;
    const int z  = blockIdx.z;
    const int m0 = mt * 32;
    const int n0 = nt * 64;

    const char* __restrict__ Xg = reinterpret_cast<const char*>(g_X16[z]);
    const char* __restrict__ Wg = reinterpret_cast<const char*>(g_W16[z]);
    float* __restrict__ C = z ? g_hb : g_ha;

    const int tid  = threadIdx.x;
    const int wid  = tid >> 5;
    const int lane = tid & 31;
    const int wm   = wid & 1;
    const int wn   = wid >> 1;

    const int a_row = tid >> 3;
    const int a_seg = tid & 7;
    const unsigned aDst = a_row * 128u + a_seg * 16u;
    const int b_row0 = tid >> 3;
    const int b_row1 = (tid + 256) >> 3;
    const int b_seg  = tid & 7;
    const unsigned bDst0 = b_row0 * 128u + b_seg * 16u;
    const unsigned bDst1 = b_row1 * 128u + b_seg * 16u;

    auto fill = [&](int c, int buf) {
        cp16(sbase + SA_OFF(buf) + aDst,
             Xg + (size_t)(c * NR + m0 + a_row) * 128 + a_seg * 16);
        cp16(sbase + SB_OFF(buf) + bDst0,
             Wg + (size_t)(c * HIDN + n0 + b_row0) * 128 + b_seg * 16);
        cp16(sbase + SB_OFF(buf) + bDst1,
             Wg + (size_t)(c * HIDN + n0 + b_row1) * 128 + b_seg * 16);
        cp_commit();
    };

    fill(0, 0);
    fill(1, 1);

    const int a_r  = (lane & 15);
    const int a_ch = (lane >> 4);
    const int b_n  = (lane & 7) + ((lane >> 4) << 3);
    const int b_ch = (lane >> 3) & 1;

    float acc[2][4];
    #pragma unroll
    for (int ni = 0; ni < 2; ni++)
        #pragma unroll
        for (int r = 0; r < 4; r++) acc[ni][r] = 0.0f;

    #pragma unroll 1
    for (int t = 0; t < NCH; t++) {
        if (t < NCH - 1) cp_wait1(); else cp_wait0();
        __syncthreads();
        if (t + 2 < NCH) fill(t + 2, (t + 2) % 3);

        const unsigned aH = sbase + SA_OFF(t % 3);
        const unsigned bH = sbase + SB_OFF(t % 3);

        #pragma unroll
        for (int ks = 0; ks < 4; ks++) {
            const unsigned kb = (unsigned)(ks * 32);
            uint32_t ah[4];
            {
                const unsigned off = sw128(
                    (unsigned)((wm * 16 + a_r) * 128) + kb + a_ch * 16);
                ldsm_x4(ah[0], ah[1], ah[2], ah[3], aH + off);
            }
            uint32_t bh[4];
            {
                const unsigned off = sw128(
                    (unsigned)((wn * 16 + b_n) * 128) + kb + b_ch * 16);
                ldsm_x4(bh[0], bh[1], bh[2], bh[3], bH + off);
            }
            #pragma unroll
            for (int ni = 0; ni < 2; ni++)
                mma_f16(acc[ni], ah[0], ah[1], ah[2], ah[3],
                        bh[2 * ni], bh[2 * ni + 1]);
        }
    }

    #pragma unroll
    for (int ni = 0; ni < 2; ni++) {
        const int row = m0 + wm * 16 + (lane >> 2);
        const int col = n0 + wn * 16 + ni * 8 + (lane & 3) * 2;
        float2 bias = make_float2(0.f, 0.f);
        if (z == 0)
            bias = *reinterpret_cast<const float2*>(&b1[col]);
        float2 o0, o1;
        o0.x = acc[ni][0] + bias.x;
        o0.y = acc[ni][1] + bias.y;
        o1.x = acc[ni][2] + bias.x;
        o1.y = acc[ni][3] + bias.y;
        *reinterpret_cast<float2*>(&C[(size_t)row * HIDN + col]) = o0;
        *reinterpret_cast<float2*>(&C[(size_t)(row + 8) * HIDN + col]) = o1;
    }
}

// ---------------------------------------------------------------------------
// Stage 2: out[i,j,b,c] = sum_h relu(ha'[i,b,h]+hb[j,b,h])*W2[c,h]+b2[c]
// Grid (3,3,16)=144, 512 threads. In-block h-split: tid<256 -> h[0:64),
// tid>=256 -> h[64:128). Each half runs the packed-f32x2 2x2 micro-tile over
// 16 hq iters; upper half deposits partials in smem; lower half adds + writes.
// 16 warps/block = 4 warps/SMSP (vs 2 before).
// ---------------------------------------------------------------------------
#define TI 32
#define TJ 32
#define PADH 132  // 128+4 floats

__global__ __launch_bounds__(512) void stage2_kernel(
    const float* __restrict__ W2, const float* __restrict__ b2,
    float* __restrict__ out)
{
    __shared__ float sA[TI][PADH];
    __shared__ float sB[TJ][PADH];
    __shared__ float sW2[2 * HIDN];
    __shared__ float sRed[256][8];

    const int i0  = blockIdx.x * TI;
    const int j0  = blockIdx.y * TJ;
    const int b   = blockIdx.z;
    const int tid = threadIdx.x;

    // Fill smem: 1024 float4 each for A and B with 512 threads -> 2/thread.
    #pragma unroll
    for (int p = 0; p < 2; p++) {
        const int q   = tid + p * 512;  // 0..1023
        const int row = q >> 5;         // 0..31
        const int hq  = q & 31;
        float4 va = *reinterpret_cast<const float4*>(
            &g_ha[((size_t)(i0 + row) * BB + b) * HIDN + hq * 4]);
        *reinterpret_cast<float4*>(&sA[row][hq * 4]) = va;
        float4 vb = *reinterpret_cast<const float4*>(
            &g_hb[((size_t)(j0 + row) * BB + b) * HIDN + hq * 4]);
        *reinterpret_cast<float4*>(&sB[row][hq * 4]) = vb;
    }
    if (tid < 64) {
        float4 w = *reinterpret_cast<const float4*>(&W2[tid * 4]);
        *reinterpret_cast<float4*>(&sW2[tid * 4]) = w;
    }
    __syncthreads();

    const int hh = tid >> 8;        // 0 or 1: h-half
    const int t  = tid & 255;
    const int rg = t >> 4;          // 0..15 -> i rows rg, rg+16
    const int cg = t & 15;          // 0..15 -> j cols cg, cg+16
    const int hq0 = hh * 16;        // start f4-group

    unsigned long long acc[2][2][2];
    #pragma unroll
    for (int ii = 0; ii < 2; ii++)
        #pragma unroll
        for (int jj = 0; jj < 2; jj++) {
            acc[ii][jj][0] = 0ull;
            acc[ii][jj][1] = 0ull;
        }

    #pragma unroll
    for (int hi = 0; hi < 16; hi++) {
        const int hq = hq0 + hi;
        ulonglong2 a0 = *reinterpret_cast<const ulonglong2*>(&sA[rg][hq * 4]);
        ulonglong2 a1 = *reinterpret_cast<const ulonglong2*>(&sA[rg + 16][hq * 4]);
        ulonglong2 q0 = *reinterpret_cast<const ulonglong2*>(&sB[cg][hq * 4]);
        ulonglong2 q1 = *reinterpret_cast<const ulonglong2*>(&sB[cg + 16][hq * 4]);
        ulonglong2 w0 = *reinterpret_cast<const ulonglong2*>(&sW2[hq * 4]);
        ulonglong2 w1 = *reinterpret_cast<const ulonglong2*>(&sW2[HIDN + hq * 4]);

        const unsigned long long av[2][2] = {{a0.x, a0.y}, {a1.x, a1.y}};
        const unsigned long long qv[2][2] = {{q0.x, q0.y}, {q1.x, q1.y}};
        const unsigned long long wv[2][2] = {{w0.x, w0.y}, {w1.x, w1.y}};

        #pragma unroll
        for (int hp = 0; hp < 2; hp++) {
            #pragma unroll
            for (int ii = 0; ii < 2; ii++)
                #pragma unroll
                for (int jj = 0; jj < 2; jj++) {
                    unsigned long long v = relu2(add2(av[ii][hp], qv[jj][hp]));
                    acc[ii][jj][0] = ffma2(v, wv[0][hp], acc[ii][jj][0]);
                    acc[ii][jj][1] = ffma2(v, wv[1][hp], acc[ii][jj][1]);
                }
        }
    }

    // Horizontal add -> 8 scalars per thread
    float res[2][2][2];
    #pragma unroll
    for (int ii = 0; ii < 2; ii++)
        #pragma unroll
        for (int jj = 0; jj < 2; jj++) {
            float2 p0 = unpk2(acc[ii][jj][0]);
            float2 p1 = unpk2(acc[ii][jj][1]);
            res[ii][jj][0] = p0.x + p0.y;
            res[ii][jj][1] = p1.x + p1.y;
        }

    // In-block reduction: upper half deposits, lower half adds + writes out.
    if (hh == 1) {
        #pragma unroll
        for (int ii = 0; ii < 2; ii++)
            #pragma unroll
            for (int jj = 0; jj < 2; jj++) {
                sRed[t][ii * 4 + jj * 2 + 0] = res[ii][jj][0];
                sRed[t][ii * 4 + jj * 2 + 1] = res[ii][jj][1];
            }
    }
    __syncthreads();
    if (hh == 0) {
        const float bb0 = b2[0];
        const float bb1 = b2[1];
        #pragma unroll
        for (int ii = 0; ii < 2; ii++)
            #pragma unroll
            for (int jj = 0; jj < 2; jj++) {
                const int i = i0 + rg + ii * 16;
                const int j = j0 + cg + jj * 16;
                const size_t idx = (((size_t)i * SS + j) * BB + b) * 2;
                float2 o;
                o.x = res[ii][jj][0] + sRed[t][ii * 4 + jj * 2 + 0] + bb0;
                o.y = res[ii][jj][1] + sRed[t][ii * 4 + jj * 2 + 1] + bb1;
                *reinterpret_cast<float2*>(&out[idx]) = o;
            }
    }
}

// ---------------------------------------------------------------------------
// Inputs: embeds, umask, qmask, embeds_cmp, W1, b1, W2, b2
// ---------------------------------------------------------------------------
extern "C" void kernel_launch(void* const* d_in, const int* in_sizes, int n_in,
                              void* d_out, int out_size)
{
    const float* embeds     = (const float*)d_in[0];
    const float* embeds_cmp = (const float*)d_in[3];
    const float* W1         = (const float*)d_in[4];
    const float* b1         = (const float*)d_in[5];
    const float* W2         = (const float*)d_in[6];
    const float* b2         = (const float*)d_in[7];
    float* out = (float*)d_out;

    cudaFuncSetAttribute(stage1_kernel,
                         cudaFuncAttributeMaxDynamicSharedMemorySize, S1_SMEM);

    const int prep_blocks = (PREP_X_THREADS + PREP_W_THREADS + 255) / 256;
    prep_kernel<<<prep_blocks, 256>>>(embeds, embeds_cmp, W1);
    stage1_kernel<<<dim3(48, 2, 2), 256, S1_SMEM>>>(b1);
    stage2_kernel<<<dim3(3, 3, 16), 512>>>(W2, b2, out);
}